// round 14
// baseline (speedup 1.0000x reference)
#include <cuda_runtime.h>
#include <cuda_bf16.h>
#include <cstdint>

#define BSZ 8192
#define DIM 128

#define NCTA  128         // one wave (<=148 SMs): 64 gram + 64 quad CTAs
#define GCTAS 64
#define QCTAS 64
#define GROWS 128         // Y rows per gram CTA
#define QROWS 128         // X rows per quad CTA
#define NTHR  512

#define XBP 68            // bf16 row pitch (words): 64 + 4 pad
#define YBP 68
#define BGP 68

// smem word offsets (max usage = quad role: 177.7 KB)
#define OFF_XB   0                               // quad: X bf16 [2*128][XBP]; gram: Y bf16 [2*128][YBP]
#define OFF_G    (OFF_XB + 2 * QROWS * XBP)      // quad: staged G [3*128][BGP]
#define OFF_P    (OFF_G + 3 * DIM * BGP)         // [6][128] = 768 w
#define OFF_COS  (OFF_P + 768)                   // [128]
#define SMEM_WORDS (OFF_COS + 128)
#define FUSED_SMEM_BYTES (SMEM_WORDS * 4)

__device__ uint32_t         g_gram_part_bf[GCTAS][3][DIM][DIM / 2]; // bf16x2 partials (6.3MB)
__device__ __nv_bfloat16    g_gramT[3][DIM][DIM];                   // G^T, bf16
__device__ float            g_loss_part[QCTAS];
__device__ int              g_flag[GCTAS];                          // producer publish flags
__device__ int              g_ctr2, g_ctr3;                         // zero-init; last CTA resets

// ---------------------------------------------------------------------------
__device__ __forceinline__ void mma_bf16(float* d, const uint32_t* a, uint32_t b0, uint32_t b1) {
    asm volatile(
        "mma.sync.aligned.m16n8k16.row.col.f32.bf16.bf16.f32 "
        "{%0,%1,%2,%3}, {%4,%5,%6,%7}, {%8,%9}, {%0,%1,%2,%3};"
        : "+f"(d[0]), "+f"(d[1]), "+f"(d[2]), "+f"(d[3])
        : "r"(a[0]), "r"(a[1]), "r"(a[2]), "r"(a[3]), "r"(b0), "r"(b1));
}
__device__ __forceinline__ void ldsm_x4(uint32_t* r, uint32_t addr) {
    asm volatile("ldmatrix.sync.aligned.m8n8.x4.shared.b16 {%0,%1,%2,%3}, [%4];"
        : "=r"(r[0]), "=r"(r[1]), "=r"(r[2]), "=r"(r[3]) : "r"(addr));
}
__device__ __forceinline__ void ldsm_x4_trans(uint32_t* r, uint32_t addr) {
    asm volatile("ldmatrix.sync.aligned.m8n8.x4.trans.shared.b16 {%0,%1,%2,%3}, [%4];"
        : "=r"(r[0]), "=r"(r[1]), "=r"(r[2]), "=r"(r[3]) : "r"(addr));
}
__device__ __forceinline__ uint32_t smem_u32(const void* p) {
    uint32_t a;
    asm("{ .reg .u64 t; cvta.to.shared.u64 t, %1; cvt.u32.u64 %0, t; }" : "=r"(a) : "l"(p));
    return a;
}
__device__ __forceinline__ void cp16(uint32_t dst, const void* src) {
    asm volatile("cp.async.cg.shared.global [%0], [%1], 16;" :: "r"(dst), "l"(src));
}
#define CP_COMMIT() asm volatile("cp.async.commit_group;" ::: "memory")
#define CP_WAIT(n)  asm volatile("cp.async.wait_group %0;" :: "n"(n) : "memory")

__device__ __forceinline__ void grid_arrive(int* ctr, int tid) {
    __threadfence();
    __syncthreads();
    if (tid == 0) atomicAdd(ctr, 1);
}
__device__ __forceinline__ void grid_spin(int* ctr, int target, int tid) {
    if (tid == 0) {
        while (*(volatile int*)ctr < target) __nanosleep(32);
    }
    __syncthreads();
    __threadfence();
}
__device__ __forceinline__ uint32_t flag_acquire(const int* p) {
    uint32_t f;
    asm volatile("ld.acquire.gpu.global.b32 %0, [%1];" : "=r"(f) : "l"(p));
    return f;
}

// ============================================================================
__global__ void __launch_bounds__(NTHR) fused_kernel(const float* __restrict__ zxs,
                                                     const float* __restrict__ zys,
                                                     const float* __restrict__ zxt,
                                                     const float* __restrict__ zyt,
                                                     float* __restrict__ out) {
    extern __shared__ uint32_t smw[];
    float* sP   = (float*)(smw + OFF_P);
    float* sCos = (float*)(smw + OFF_COS);
    __shared__ int sLast;

    const int tid  = threadIdx.x;
    const int wid  = tid >> 5;
    const int lane = tid & 31;
    const int gid  = lane >> 2;
    const int tg   = lane & 3;
    const int fl   = lane & 15;            // ldmatrix row-lane (non-trans)
    const int kh   = (lane >> 4) << 2;     // ldmatrix k-half (non-trans)
    const int sRow = (lane & 7) + ((lane >> 4) << 3);  // trans-ldsm sample row
    const int fSel = ((lane >> 3) & 1) << 2;           // trans-ldsm feature half
    const int cta  = blockIdx.x;

    if (cta < GCTAS) {
        // ==================== GRAM ROLE (128 Y rows, K=128) ====================
        const int row0 = cta * GROWS;
        // load + normalize Y -> natural bf16: 4 threads/row, 32 floats each
        {
            int r = tid >> 2, part = tid & 3;
#pragma unroll 1
            for (int which = 0; which < 2; which++) {
                const float* src = which ? zyt : zys;
                const float4* s = (const float4*)(src + (size_t)(row0 + r) * DIM) + part * 8;
                float4 v[8];
                float ss = 0.f;
#pragma unroll
                for (int i = 0; i < 8; i++) {
                    v[i] = s[i];
                    ss += v[i].x * v[i].x + v[i].y * v[i].y + v[i].z * v[i].z + v[i].w * v[i].w;
                }
                ss += __shfl_xor_sync(0xffffffffu, ss, 1);
                ss += __shfl_xor_sync(0xffffffffu, ss, 2);
                float inv = rsqrtf(fmaxf(ss, 1e-24f));
                uint32_t* yb = smw + OFF_XB + (size_t)(which * GROWS + r) * YBP + part * 16;
                const float* vf = (const float*)v;
#pragma unroll
                for (int i = 0; i < 16; i++) {
                    __nv_bfloat162 h = __floats2bfloat162_rn(vf[2 * i] * inv, vf[2 * i + 1] * inv);
                    yb[i] = *(uint32_t*)&h;
                }
            }
        }
        __syncthreads();

        // gram partials via bf16 mma + trans-ldsm, warp tile 32x32, K=128
        {
            const int m0q = (wid & 3) * 32;
            const int n0q = (wid >> 2) * 32;
            const uint32_t ytb = smem_u32(smw + OFF_XB);
#pragma unroll 1
            for (int m = 0; m < 3; m++) {
                const uint32_t aB = ytb + (m == 1 ? GROWS * YBP * 4 : 0);
                const uint32_t bB = ytb + (m == 0 ? 0 : GROWS * YBP * 4);
                float acc[8][4];
#pragma unroll
                for (int t = 0; t < 8; t++)
#pragma unroll
                    for (int j = 0; j < 4; j++) acc[t][j] = 0.f;

#pragma unroll
                for (int k0 = 0; k0 < GROWS; k0 += 16) {     // 8 k-steps of 16
                    uint32_t A[2][4], B[2][4];
                    uint32_t rowOff = (uint32_t)((k0 + sRow) * YBP + fSel) * 4;
#pragma unroll
                    for (int mt = 0; mt < 2; mt++)
                        ldsm_x4_trans(A[mt], aB + rowOff + (uint32_t)((m0q + mt * 16) >> 1) * 4);
#pragma unroll
                    for (int p = 0; p < 2; p++)
                        ldsm_x4_trans(B[p], bB + rowOff + (uint32_t)((n0q + p * 16) >> 1) * 4);
#pragma unroll
                    for (int mt = 0; mt < 2; mt++)
#pragma unroll
                        for (int t = 0; t < 4; t++) {
                            int p = t >> 1, sub = t & 1;
                            mma_bf16(acc[mt * 4 + t], A[mt], B[p][sub], B[p][2 + sub]);
                        }
                }
                uint32_t* dst = &g_gram_part_bf[cta][m][0][0];
#pragma unroll
                for (int mt = 0; mt < 2; mt++) {
                    int r1 = m0q + mt * 16 + gid, r2 = r1 + 8;
#pragma unroll
                    for (int t = 0; t < 4; t++) {
                        int cw = ((n0q + t * 8) >> 1) + tg;
                        __nv_bfloat162 h1 = __floats2bfloat162_rn(acc[mt * 4 + t][0], acc[mt * 4 + t][1]);
                        __nv_bfloat162 h2 = __floats2bfloat162_rn(acc[mt * 4 + t][2], acc[mt * 4 + t][3]);
                        dst[r1 * (DIM / 2) + cw] = *(uint32_t*)&h1;
                        dst[r2 * (DIM / 2) + cw] = *(uint32_t*)&h2;
                    }
                }
            }
        }
        // publish (release) and exit
        __threadfence();
        __syncthreads();
        if (tid == 0) atomicExch(&g_flag[cta], 1);
        return;
    }

    // ==================== QUAD ROLE (128 X rows) ====================
    const int qb = cta - GCTAS;
    const int row0 = qb * QROWS;

    // load + normalize X directly (runs in parallel with gram CTAs)
    {
        int r = tid >> 2, part = tid & 3;
#pragma unroll 1
        for (int which = 0; which < 2; which++) {
            const float* src = which ? zxt : zxs;
            const float4* s = (const float4*)(src + (size_t)(row0 + r) * DIM) + part * 8;
            float4 v[8];
            float ss = 0.f;
#pragma unroll
            for (int i = 0; i < 8; i++) {
                v[i] = s[i];
                ss += v[i].x * v[i].x + v[i].y * v[i].y + v[i].z * v[i].z + v[i].w * v[i].w;
            }
            ss += __shfl_xor_sync(0xffffffffu, ss, 1);
            ss += __shfl_xor_sync(0xffffffffu, ss, 2);
            float inv = rsqrtf(fmaxf(ss, 1e-24f));
            uint32_t* xb = smw + OFF_XB + (size_t)(which * QROWS + r) * XBP + part * 16;
            const float* vf = (const float*)v;
#pragma unroll
            for (int i = 0; i < 16; i++) {
                __nv_bfloat162 h = __floats2bfloat162_rn(vf[2 * i] * inv, vf[2 * i + 1] * inv);
                xb[i] = *(uint32_t*)&h;
            }
        }
    }

    // ---- streaming reduce of this CTA's 384-pair G slice (fixed order) ----
    if (tid < 384) {                        // warps 0..11 (uniform per warp)
        int e = qb * 384 + tid;
        const uint32_t* base = &g_gram_part_bf[0][0][0][0];
        float s0 = 0.f, s1 = 0.f;
#pragma unroll 1
        for (int chunk = 0; chunk < 2; chunk++) {
            int p0 = chunk * 32;
            for (;;) {
                uint32_t f = flag_acquire(&g_flag[p0 + lane]);
                if (__all_sync(0xffffffffu, f != 0)) break;
                __nanosleep(64);
            }
#pragma unroll 8
            for (int p = p0; p < p0 + 32; p++) {
                uint32_t u = base[(size_t)p * (3 * DIM * (DIM / 2)) + e];
                float2 f = __bfloat1622float2(*(__nv_bfloat162*)&u);
                s0 += f.x; s1 += f.y;
            }
        }
        int mat = e >> 13, rem = e & 8191, a = rem >> 6, pw = rem & 63;
        g_gramT[mat][2 * pw][a]     = __float2bfloat16(s0);
        g_gramT[mat][2 * pw + 1][a] = __float2bfloat16(s1);
    }
    grid_arrive(&g_ctr2, tid);
    grid_spin(&g_ctr2, QCTAS, tid);

    // ---- stage all 3 G mats (cp.async), then quad forms ----
    {
        const uint32_t gb = smem_u32(smw + OFF_G);
        {
            const char* gsrc = (const char*)&g_gramT[0][0][0];
#pragma unroll
            for (int i = 0; i < 12; i++) {
                int idx = tid + i * NTHR;               // 6144 x 16B
                int mat = idx >> 11;
                int rem = idx & 2047;
                int row = rem >> 4, c = rem & 15;
                cp16(gb + (uint32_t)((mat * DIM + row) * BGP * 4 + c * 16), gsrc + idx * 16);
            }
        }
        CP_COMMIT();
        CP_WAIT(0);
        __syncthreads();

        const int m0 = (wid & 7) * 16;     // 8 m-strips of 16 rows
        const int nh = (wid >> 3) * 64;    // 2 n-halves of 64 cols
        const uint32_t xbb = smem_u32(smw + OFF_XB);

#pragma unroll 1
        for (int m = 0; m < 3; m++) {
            const uint32_t bGb = gb + (uint32_t)(m * DIM * BGP) * 4;
            const uint32_t xab = xbb + (m == 1 ? QROWS * XBP * 4 : 0);
            const uint32_t* Xb = smw + OFF_XB + (m == 0 ? 0 : QROWS * XBP);

            float acc[8][4];
#pragma unroll
            for (int t = 0; t < 8; t++)
#pragma unroll
                for (int j = 0; j < 4; j++) acc[t][j] = 0.f;

#pragma unroll
            for (int k0h = 0; k0h < 64; k0h += 8) {      // 8 k-steps of 16
                uint32_t A[4], B[4][4];
                ldsm_x4(A, xab + (uint32_t)((m0 + fl) * XBP + k0h + kh) * 4);
#pragma unroll
                for (int p = 0; p < 4; p++) {
                    int f = nh + p * 16 + fl;
                    ldsm_x4(B[p], bGb + (uint32_t)(f * BGP + k0h + kh) * 4);
                }
#pragma unroll
                for (int t = 0; t < 8; t++) {
                    int p = t >> 1, sub = t & 1;
                    mma_bf16(acc[t], A, B[p][sub], B[p][2 + sub]);
                }
            }

            float p1 = 0.f, p2 = 0.f;
#pragma unroll
            for (int t = 0; t < 8; t++) {
                int n0 = nh + t * 8;
                uint32_t xw1 = Xb[(m0 + gid) * XBP + (n0 >> 1) + tg];
                uint32_t xw2 = Xb[(m0 + 8 + gid) * XBP + (n0 >> 1) + tg];
                float2 f1 = __bfloat1622float2(*(__nv_bfloat162*)&xw1);
                float2 f2 = __bfloat1622float2(*(__nv_bfloat162*)&xw2);
                p1 += acc[t][0] * f1.x + acc[t][1] * f1.y;
                p2 += acc[t][2] * f2.x + acc[t][3] * f2.y;
            }
            p1 += __shfl_xor_sync(0xffffffffu, p1, 1);
            p1 += __shfl_xor_sync(0xffffffffu, p1, 2);
            p2 += __shfl_xor_sync(0xffffffffu, p2, 1);
            p2 += __shfl_xor_sync(0xffffffffu, p2, 2);
            if (tg == 0) {
                int hsel = wid >> 3;
                sP[(m * 2 + hsel) * QROWS + m0 + gid]     = p1;
                sP[(m * 2 + hsel) * QROWS + m0 + 8 + gid] = p2;
            }
        }
    }
    __syncthreads();

    // ---- cosines + per-CTA partial ----
    if (tid < QROWS) {
        float A = sP[0 * QROWS + tid] + sP[1 * QROWS + tid];
        float B = sP[2 * QROWS + tid] + sP[3 * QROWS + tid];
        float C = sP[4 * QROWS + tid] + sP[5 * QROWS + tid];
        sCos[tid] = C * rsqrtf(fmaxf(A * B, 1e-30f));
    }
    __syncthreads();
    if (tid == 0) {
        float s = 0.f;
#pragma unroll 8
        for (int i = 0; i < QROWS; i++) s += sCos[i];
        g_loss_part[qb] = s;
        __threadfence();
        int v = atomicAdd(&g_ctr3, 1);
        sLast = (v == QCTAS - 1);
    }
    __syncthreads();

    // ---- last quad CTA: final reduction, write loss, reset flags+counters ----
    if (sLast) {
        __threadfence();
        __shared__ float w[2];
        if (tid < QCTAS) {
            float v = g_loss_part[tid];
#pragma unroll
            for (int off = 16; off > 0; off >>= 1)
                v += __shfl_xor_sync(0xffffffffu, v, off);
            if ((tid & 31) == 0) w[tid >> 5] = v;
            g_flag[tid] = 0;                  // reset publish flags (64)
        }
        __syncthreads();
        if (tid == 0) {
            float s = w[0] + w[1];
            const float b = (float)BSZ;
            out[0] = (2.f * b - 2.f * s) / (b * b);
            g_ctr2 = 0; g_ctr3 = 0;           // reset for next graph replay
            __threadfence();
        }
    }
}

// ============================================================================
extern "C" void kernel_launch(void* const* d_in, const int* in_sizes, int n_in,
                              void* d_out, int out_size) {
    (void)in_sizes; (void)n_in; (void)out_size;
    const float* zxs = (const float*)d_in[0];
    const float* zys = (const float*)d_in[1];
    const float* zxt = (const float*)d_in[2];
    const float* zyt = (const float*)d_in[3];
    // temperature (d_in[4]) cancels exactly under row-normalization.

    cudaFuncSetAttribute(fused_kernel, cudaFuncAttributeMaxDynamicSharedMemorySize,
                         FUSED_SMEM_BYTES);

    fused_kernel<<<NCTA, NTHR, FUSED_SMEM_BYTES>>>(zxs, zys, zxt, zyt, (float*)d_out);
}

// round 15
// speedup vs baseline: 1.1893x; 1.1893x over previous
#include <cuda_runtime.h>
#include <cuda_bf16.h>
#include <cstdint>

#define BSZ 8192
#define DIM 128

#define NCTA 128          // one wave: <=148 SMs, 1 CTA/SM (grid-sync safe)
#define ROWS 64           // rows of each tensor per CTA
#define NTHR 512

// shared-memory word (4B) pitches
#define XBP 68            // X bf16 rows: 64 words + 4 pad
#define YBP 68            // Y bf16 rows (natural layout)
#define BGP 68            // staged G^T bf16 rows
#define XRP 132           // raw fp32 X staging pitch

// smem word offsets
#define OFF_XB   0                              // [2][64][XBP] = 8704 w (X bf16, resident)
#define OFF_G    (OFF_XB + 2 * ROWS * XBP)      // 26112 w: G stage region.
                                                //   phases 0-2: Y bf16 [2][64][YBP] at +0,
                                                //               X raw  [2][64][XRP] at +8704
#define OFF_XRAW (OFF_G + 2 * ROWS * YBP)
#define OFF_P    (OFF_G + 3 * DIM * BGP)        // 768 w (phase-2 sRed / phase-3 sP)
#define OFF_COS  (OFF_P + 12 * ROWS)            // [64]
#define SMEM_WORDS (OFF_COS + ROWS)
#define FUSED_SMEM_BYTES (SMEM_WORDS * 4)       // ~139 KB

__device__ uint32_t         g_gram_part_bf[NCTA][3][DIM][DIM / 2]; // bf16x2 partials
__device__ __nv_bfloat16    g_gramT[3][DIM][DIM];                  // G^T, bf16 (128 x 768B slices)
__device__ float            g_loss_part[NCTA];
__device__ int              g_flag2[NCTA];                         // per-CTA G-slice publish flags
__device__ int              g_ctr1, g_ctr3;                        // zero-init; last CTA resets

// ---------------------------------------------------------------------------
__device__ __forceinline__ void mma_bf16(float* d, const uint32_t* a, uint32_t b0, uint32_t b1) {
    asm volatile(
        "mma.sync.aligned.m16n8k16.row.col.f32.bf16.bf16.f32 "
        "{%0,%1,%2,%3}, {%4,%5,%6,%7}, {%8,%9}, {%0,%1,%2,%3};"
        : "+f"(d[0]), "+f"(d[1]), "+f"(d[2]), "+f"(d[3])
        : "r"(a[0]), "r"(a[1]), "r"(a[2]), "r"(a[3]), "r"(b0), "r"(b1));
}
__device__ __forceinline__ void ldsm_x4(uint32_t* r, uint32_t addr) {
    asm volatile("ldmatrix.sync.aligned.m8n8.x4.shared.b16 {%0,%1,%2,%3}, [%4];"
        : "=r"(r[0]), "=r"(r[1]), "=r"(r[2]), "=r"(r[3]) : "r"(addr));
}
__device__ __forceinline__ void ldsm_x4_trans(uint32_t* r, uint32_t addr) {
    asm volatile("ldmatrix.sync.aligned.m8n8.x4.trans.shared.b16 {%0,%1,%2,%3}, [%4];"
        : "=r"(r[0]), "=r"(r[1]), "=r"(r[2]), "=r"(r[3]) : "r"(addr));
}
__device__ __forceinline__ uint32_t smem_u32(const void* p) {
    uint32_t a;
    asm("{ .reg .u64 t; cvta.to.shared.u64 t, %1; cvt.u32.u64 %0, t; }" : "=r"(a) : "l"(p));
    return a;
}
__device__ __forceinline__ void cp16(uint32_t dst, const void* src) {
    asm volatile("cp.async.cg.shared.global [%0], [%1], 16;" :: "r"(dst), "l"(src));
}
#define CP_COMMIT() asm volatile("cp.async.commit_group;" ::: "memory")
#define CP_WAIT(n)  asm volatile("cp.async.wait_group %0;" :: "n"(n) : "memory")

__device__ __forceinline__ void grid_arrive(int* ctr, int tid) {
    __threadfence();
    __syncthreads();
    if (tid == 0) atomicAdd(ctr, 1);
}
__device__ __forceinline__ void grid_spin(int* ctr, int target, int tid) {
    if (tid == 0) {
        while (*(volatile int*)ctr < target) __nanosleep(32);
    }
    __syncthreads();
    __threadfence();
}
__device__ __forceinline__ uint32_t flag_acquire(const int* p) {
    uint32_t f;
    asm volatile("ld.acquire.gpu.global.b32 %0, [%1];" : "=r"(f) : "l"(p));
    return f;
}

// ============================================================================
__global__ void __launch_bounds__(NTHR) fused_kernel(const float* __restrict__ zxs,
                                                     const float* __restrict__ zys,
                                                     const float* __restrict__ zxt,
                                                     const float* __restrict__ zyt,
                                                     float* __restrict__ out) {
    extern __shared__ uint32_t smw[];
    float* sP   = (float*)(smw + OFF_P);     // phase-2 sRed, then phase-3 partials
    float* sCos = (float*)(smw + OFF_COS);
    __shared__ int sLast;

    const int tid  = threadIdx.x;
    const int wid  = tid >> 5;
    const int lane = tid & 31;
    const int gid  = lane >> 2;
    const int tg   = lane & 3;
    const int fl   = lane & 15;            // ldmatrix row-lane (non-trans)
    const int kh   = (lane >> 4) << 2;     // ldmatrix k-half (non-trans)
    const int sRow = (lane & 7) + ((lane >> 4) << 3);  // trans-ldsm sample row
    const int fSel = ((lane >> 3) & 1) << 2;           // trans-ldsm feature half (words)
    const int cta  = blockIdx.x;
    const int row0 = cta * ROWS;

    // ---- prefetch raw fp32 X into smem (overlaps the entire gram phase) ----
    {
        const uint32_t xrb = smem_u32(smw + OFF_XRAW);
#pragma unroll
        for (int i = 0; i < 8; i++) {
            int idx = tid + i * NTHR;         // 4096 x 16B chunks
            int which = idx >> 11;
            int rem = idx & 2047;
            int row = rem >> 5, c = rem & 31;
            const float* src = (which ? zxt : zxs) + (size_t)(row0 + row) * DIM + c * 4;
            cp16(xrb + (uint32_t)((which * ROWS + row) * XRP + c * 4) * 4, src);
        }
        CP_COMMIT();
    }

    // ---- phase 0: load + normalize Y -> natural bf16 (packed stores) ----
    {
        int r = tid >> 3, part = tid & 7;
#pragma unroll 1
        for (int which = 0; which < 2; which++) {
            const float* src = which ? zyt : zys;
            const float4* s = (const float4*)(src + (size_t)(row0 + r) * DIM) + part * 4;
            float4 v[4];
            float ss = 0.f;
#pragma unroll
            for (int i = 0; i < 4; i++) {
                v[i] = s[i];
                ss += v[i].x * v[i].x + v[i].y * v[i].y + v[i].z * v[i].z + v[i].w * v[i].w;
            }
            ss += __shfl_xor_sync(0xffffffffu, ss, 1);
            ss += __shfl_xor_sync(0xffffffffu, ss, 2);
            ss += __shfl_xor_sync(0xffffffffu, ss, 4);
            float inv = rsqrtf(fmaxf(ss, 1e-24f));
            uint32_t* yb = smw + OFF_G + (size_t)(which * ROWS + r) * YBP + part * 8;
            const float* vf = (const float*)v;
#pragma unroll
            for (int i = 0; i < 8; i++) {
                __nv_bfloat162 h = __floats2bfloat162_rn(vf[2 * i] * inv, vf[2 * i + 1] * inv);
                yb[i] = *(uint32_t*)&h;
            }
        }
    }
    __syncthreads();

    // ---- phase 1: gram partials via bf16 mma + trans-ldsm, warp tile 32x32 ----
    {
        const int m0q = (wid & 3) * 32;
        const int n0q = (wid >> 2) * 32;
        const uint32_t ytb = smem_u32(smw + OFF_G);
#pragma unroll 1
        for (int m = 0; m < 3; m++) {
            const uint32_t aB = ytb + (m == 1 ? ROWS * YBP * 4 : 0);
            const uint32_t bB = ytb + (m == 0 ? 0 : ROWS * YBP * 4);
            float acc[8][4];
#pragma unroll
            for (int t = 0; t < 8; t++)
#pragma unroll
                for (int j = 0; j < 4; j++) acc[t][j] = 0.f;

#pragma unroll
            for (int k0 = 0; k0 < ROWS; k0 += 16) {     // k-step = 16 samples
                uint32_t A[2][4], B[2][4];
                uint32_t rowOff = (uint32_t)((k0 + sRow) * YBP + fSel) * 4;
#pragma unroll
                for (int mt = 0; mt < 2; mt++)
                    ldsm_x4_trans(A[mt], aB + rowOff + (uint32_t)((m0q + mt * 16) >> 1) * 4);
#pragma unroll
                for (int p = 0; p < 2; p++)
                    ldsm_x4_trans(B[p], bB + rowOff + (uint32_t)((n0q + p * 16) >> 1) * 4);
#pragma unroll
                for (int mt = 0; mt < 2; mt++)
#pragma unroll
                    for (int t = 0; t < 4; t++) {
                        int p = t >> 1, sub = t & 1;
                        mma_bf16(acc[mt * 4 + t], A[mt], B[p][sub], B[p][2 + sub]);
                    }
            }
            uint32_t* dst = &g_gram_part_bf[cta][m][0][0];
#pragma unroll
            for (int mt = 0; mt < 2; mt++) {
                int r1 = m0q + mt * 16 + gid, r2 = r1 + 8;
#pragma unroll
                for (int t = 0; t < 4; t++) {
                    int cw = ((n0q + t * 8) >> 1) + tg;
                    __nv_bfloat162 h1 = __floats2bfloat162_rn(acc[mt * 4 + t][0], acc[mt * 4 + t][1]);
                    __nv_bfloat162 h2 = __floats2bfloat162_rn(acc[mt * 4 + t][2], acc[mt * 4 + t][3]);
                    dst[r1 * (DIM / 2) + cw] = *(uint32_t*)&h1;
                    dst[r2 * (DIM / 2) + cw] = *(uint32_t*)&h2;
                }
            }
        }
    }

    // ---- arrive barrier 1; convert prefetched X (already in smem) ----
    grid_arrive(&g_ctr1, tid);
    CP_WAIT(0);
    __syncthreads();
    {
        int r = tid >> 3, part = tid & 7;
#pragma unroll 1
        for (int which = 0; which < 2; which++) {
            const float* xr = (const float*)(smw + OFF_XRAW + (size_t)(which * ROWS + r) * XRP);
            float4 v[4];
            float ss = 0.f;
#pragma unroll
            for (int i = 0; i < 4; i++) {
                v[i] = *(const float4*)(xr + part * 4 + i * 32);
                ss += v[i].x * v[i].x + v[i].y * v[i].y + v[i].z * v[i].z + v[i].w * v[i].w;
            }
            ss += __shfl_xor_sync(0xffffffffu, ss, 1);
            ss += __shfl_xor_sync(0xffffffffu, ss, 2);
            ss += __shfl_xor_sync(0xffffffffu, ss, 4);
            float inv = rsqrtf(fmaxf(ss, 1e-24f));
            uint32_t* xb = smw + OFF_XB + (size_t)(which * ROWS + r) * XBP;
#pragma unroll
            for (int i = 0; i < 4; i++) {
                __nv_bfloat162 h0 = __floats2bfloat162_rn(v[i].x * inv, v[i].y * inv);
                __nv_bfloat162 h1 = __floats2bfloat162_rn(v[i].z * inv, v[i].w * inv);
                xb[part * 2 + i * 16]     = *(uint32_t*)&h0;
                xb[part * 2 + i * 16 + 1] = *(uint32_t*)&h1;
            }
        }
    }
    grid_spin(&g_ctr1, NCTA, tid);

    // ---- phase 2: reduce bf16 partials (fixed order), write G^T slice ----
    {
        if (tid < 384) {
            int t192 = tid % 192;
            int half = tid / 192;
            int e = cta * 192 + t192;
            const uint32_t* base = &g_gram_part_bf[0][0][0][0]
                                 + (size_t)(half * 64) * (3 * DIM * (DIM / 2));
            float s0 = 0.f, s1 = 0.f;
#pragma unroll 16
            for (int p = 0; p < 64; p++) {
                uint32_t u = base[(size_t)p * (3 * DIM * (DIM / 2)) + e];
                float2 f = __bfloat1622float2(*(__nv_bfloat162*)&u);
                s0 += f.x; s1 += f.y;
            }
            sP[(half * 192 + t192) * 2]     = s0;
            sP[(half * 192 + t192) * 2 + 1] = s1;
        }
        __syncthreads();
        if (tid < 192) {
            int e = cta * 192 + tid;
            float a0 = sP[tid * 2]     + sP[(192 + tid) * 2];
            float a1 = sP[tid * 2 + 1] + sP[(192 + tid) * 2 + 1];
            int mat = e >> 13, rem = e & 8191, a = rem >> 6, pw = rem & 63;
            g_gramT[mat][2 * pw][a]     = __float2bfloat16(a0);
            g_gramT[mat][2 * pw + 1][a] = __float2bfloat16(a1);
        }
    }
    // publish this CTA's 768B G slice (release) — NO grid barrier 2
    __threadfence();
    __syncthreads();
    if (tid == 0) atomicExch(&g_flag2[cta], 1);

    // ---- phase 3: STREAM-stage all 128 G slices as they publish, then quad ----
    {
        const uint32_t gb = smem_u32(smw + OFF_G);
        const char* gsrc = (const char*)&g_gramT[0][0][0];
        // warp w owns slices w*8 .. w*8+7; slice p = bytes [p*768, p*768+768)
        // chunk c (16B): smem word (p*3 + c/16)*BGP + (c%16)*4
#pragma unroll 1
        for (int s = 0; s < 8; s++) {
            int p = wid * 8 + s;
            for (;;) {
                uint32_t f = flag_acquire(&g_flag2[p]);
                if (__all_sync(0xffffffffu, f != 0)) break;
                __nanosleep(32);
            }
            {
                int c = lane;
                uint32_t dst = gb + (uint32_t)(((p * 3 + (c >> 4)) * BGP + (c & 15) * 4) * 4);
                cp16(dst, gsrc + (size_t)p * 768 + c * 16);
            }
            if (lane < 16) {
                int c = 32 + lane;
                uint32_t dst = gb + (uint32_t)(((p * 3 + (c >> 4)) * BGP + (c & 15) * 4) * 4);
                cp16(dst, gsrc + (size_t)p * 768 + c * 16);
            }
        }
        CP_COMMIT();
        CP_WAIT(0);
        __syncthreads();

        const int m0 = (wid & 3) * 16;
        const int nq = wid >> 2;
        const uint32_t xbb = smem_u32(smw + OFF_XB);

#pragma unroll 1
        for (int m = 0; m < 3; m++) {
            const uint32_t bGb = gb + (uint32_t)(m * DIM * BGP) * 4;
            const uint32_t xab = xbb + (m == 1 ? ROWS * XBP * 4 : 0);
            const uint32_t* Xb = smw + OFF_XB + (m == 0 ? 0 : ROWS * XBP);

            float acc[4][4];
#pragma unroll
            for (int t = 0; t < 4; t++)
#pragma unroll
                for (int j = 0; j < 4; j++) acc[t][j] = 0.f;

#pragma unroll 2
            for (int k0h = 0; k0h < 64; k0h += 8) {      // 8 k-steps of 16
                uint32_t A[4], B[2][4];
                ldsm_x4(A, xab + (uint32_t)((m0 + fl) * XBP + k0h + kh) * 4);
#pragma unroll
                for (int p = 0; p < 2; p++) {
                    int f = nq * 32 + p * 16 + fl;
                    ldsm_x4(B[p], bGb + (uint32_t)(f * BGP + k0h + kh) * 4);
                }
#pragma unroll
                for (int t = 0; t < 4; t++) {
                    int p = t >> 1, sub = t & 1;
                    mma_bf16(acc[t], A, B[p][sub], B[p][2 + sub]);
                }
            }

            float p1 = 0.f, p2 = 0.f;
#pragma unroll
            for (int t = 0; t < 4; t++) {
                int n0 = nq * 32 + t * 8;
                uint32_t xw1 = Xb[(m0 + gid) * XBP + (n0 >> 1) + tg];
                uint32_t xw2 = Xb[(m0 + 8 + gid) * XBP + (n0 >> 1) + tg];
                float2 f1 = __bfloat1622float2(*(__nv_bfloat162*)&xw1);
                float2 f2 = __bfloat1622float2(*(__nv_bfloat162*)&xw2);
                p1 += acc[t][0] * f1.x + acc[t][1] * f1.y;
                p2 += acc[t][2] * f2.x + acc[t][3] * f2.y;
            }
            p1 += __shfl_xor_sync(0xffffffffu, p1, 1);
            p1 += __shfl_xor_sync(0xffffffffu, p1, 2);
            p2 += __shfl_xor_sync(0xffffffffu, p2, 1);
            p2 += __shfl_xor_sync(0xffffffffu, p2, 2);
            if (tg == 0) {
                sP[(m * 4 + nq) * ROWS + m0 + gid]     = p1;
                sP[(m * 4 + nq) * ROWS + m0 + 8 + gid] = p2;
            }
        }
    }
    __syncthreads();

    // ---- cosines + per-CTA partial ----
    if (tid < ROWS) {
        float A = sP[0 * ROWS + tid] + sP[1 * ROWS + tid] + sP[2 * ROWS + tid] + sP[3 * ROWS + tid];
        float B = sP[4 * ROWS + tid] + sP[5 * ROWS + tid] + sP[6 * ROWS + tid] + sP[7 * ROWS + tid];
        float C = sP[8 * ROWS + tid] + sP[9 * ROWS + tid] + sP[10 * ROWS + tid] + sP[11 * ROWS + tid];
        sCos[tid] = C * rsqrtf(fmaxf(A * B, 1e-30f));
    }
    __syncthreads();
    if (tid == 0) {
        float s = 0.f;
#pragma unroll 8
        for (int i = 0; i < ROWS; i++) s += sCos[i];
        g_loss_part[cta] = s;
        __threadfence();
        int v = atomicAdd(&g_ctr3, 1);
        sLast = (v == NCTA - 1);
    }
    __syncthreads();

    // ---- last CTA: final reduction, write loss, reset flags + counters ----
    if (sLast) {
        __threadfence();
        __shared__ float w[4];
        if (tid < NCTA) {
            float v = g_loss_part[tid];
#pragma unroll
            for (int off = 16; off > 0; off >>= 1)
                v += __shfl_xor_sync(0xffffffffu, v, off);
            if ((tid & 31) == 0) w[tid >> 5] = v;
            g_flag2[tid] = 0;                 // reset slice flags
        }
        __syncthreads();
        if (tid == 0) {
            float s = w[0] + w[1] + w[2] + w[3];
            const float b = (float)BSZ;
            out[0] = (2.f * b - 2.f * s) / (b * b);
            g_ctr1 = 0; g_ctr3 = 0;           // reset for next graph replay
            __threadfence();
        }
    }
}

// ============================================================================
extern "C" void kernel_launch(void* const* d_in, const int* in_sizes, int n_in,
                              void* d_out, int out_size) {
    (void)in_sizes; (void)n_in; (void)out_size;
    const float* zxs = (const float*)d_in[0];
    const float* zys = (const float*)d_in[1];
    const float* zxt = (const float*)d_in[2];
    const float* zyt = (const float*)d_in[3];
    // temperature (d_in[4]) cancels exactly under row-normalization.

    cudaFuncSetAttribute(fused_kernel, cudaFuncAttributeMaxDynamicSharedMemorySize,
                         FUSED_SMEM_BYTES);

    fused_kernel<<<NCTA, NTHR, FUSED_SMEM_BYTES>>>(zxs, zys, zxt, zyt, (float*)d_out);
}

// round 16
// speedup vs baseline: 1.3906x; 1.1692x over previous
#include <cuda_runtime.h>
#include <cuda_bf16.h>
#include <cstdint>

#define BSZ 8192
#define DIM 128

#define NCTA 128          // one wave: <=148 SMs, 1 CTA/SM (grid-sync safe)
#define ROWS 64           // rows of each tensor per CTA
#define NTHR 512

// shared-memory word (4B) pitches
#define XBP 68            // X bf16 rows: 64 words + 4 pad
#define YBP 68            // Y bf16 rows (natural layout)
#define BGP 68            // staged G^T bf16 rows
#define XRP 132           // raw fp32 X staging pitch

// smem word offsets
#define OFF_XB   0                              // [2][64][XBP] = 8704 w (X bf16, resident)
#define OFF_G    (OFF_XB + 2 * ROWS * XBP)      // 26112 w: G stage region.
                                                //   phases 0-2: Y bf16 [2][64][YBP] at +0,
                                                //               X raw  [2][64][XRP] at +8704
#define OFF_XRAW (OFF_G + 2 * ROWS * YBP)
#define OFF_P    (OFF_G + 3 * DIM * BGP)        // 768 w (phase-2 sRed / phase-3 sP)
#define OFF_COS  (OFF_P + 12 * ROWS)            // [64]
#define SMEM_WORDS (OFF_COS + ROWS)
#define FUSED_SMEM_BYTES (SMEM_WORDS * 4)       // ~139 KB

__device__ uint32_t         g_gram_part_bf[NCTA][3][DIM][DIM / 2]; // bf16x2 partials
__device__ __nv_bfloat16    g_gramT[3][DIM][DIM];                  // G^T, bf16
__device__ float            g_loss_part[NCTA];
__device__ int              g_ctr1, g_ctr2, g_ctr3;                // zero-init; last CTA resets

// ---------------------------------------------------------------------------
__device__ __forceinline__ void mma_bf16(float* d, const uint32_t* a, uint32_t b0, uint32_t b1) {
    asm volatile(
        "mma.sync.aligned.m16n8k16.row.col.f32.bf16.bf16.f32 "
        "{%0,%1,%2,%3}, {%4,%5,%6,%7}, {%8,%9}, {%0,%1,%2,%3};"
        : "+f"(d[0]), "+f"(d[1]), "+f"(d[2]), "+f"(d[3])
        : "r"(a[0]), "r"(a[1]), "r"(a[2]), "r"(a[3]), "r"(b0), "r"(b1));
}
__device__ __forceinline__ void ldsm_x4(uint32_t* r, uint32_t addr) {
    asm volatile("ldmatrix.sync.aligned.m8n8.x4.shared.b16 {%0,%1,%2,%3}, [%4];"
        : "=r"(r[0]), "=r"(r[1]), "=r"(r[2]), "=r"(r[3]) : "r"(addr));
}
__device__ __forceinline__ void ldsm_x4_trans(uint32_t* r, uint32_t addr) {
    asm volatile("ldmatrix.sync.aligned.m8n8.x4.trans.shared.b16 {%0,%1,%2,%3}, [%4];"
        : "=r"(r[0]), "=r"(r[1]), "=r"(r[2]), "=r"(r[3]) : "r"(addr));
}
__device__ __forceinline__ uint32_t smem_u32(const void* p) {
    uint32_t a;
    asm("{ .reg .u64 t; cvta.to.shared.u64 t, %1; cvt.u32.u64 %0, t; }" : "=r"(a) : "l"(p));
    return a;
}
__device__ __forceinline__ void cp16(uint32_t dst, const void* src) {
    asm volatile("cp.async.cg.shared.global [%0], [%1], 16;" :: "r"(dst), "l"(src));
}
#define CP_COMMIT() asm volatile("cp.async.commit_group;" ::: "memory")
#define CP_WAIT(n)  asm volatile("cp.async.wait_group %0;" :: "n"(n) : "memory")

__device__ __forceinline__ void grid_arrive(int* ctr, int tid) {
    __threadfence();
    __syncthreads();
    if (tid == 0) atomicAdd(ctr, 1);
}
__device__ __forceinline__ void grid_spin(int* ctr, int target, int tid) {
    if (tid == 0) {
        while (*(volatile int*)ctr < target) __nanosleep(32);
    }
    __syncthreads();
    __threadfence();
}

// ============================================================================
__global__ void __launch_bounds__(NTHR) fused_kernel(const float* __restrict__ zxs,
                                                     const float* __restrict__ zys,
                                                     const float* __restrict__ zxt,
                                                     const float* __restrict__ zyt,
                                                     float* __restrict__ out) {
    extern __shared__ uint32_t smw[];
    float* sP   = (float*)(smw + OFF_P);     // phase-2 sRed, then phase-3 partials
    float* sCos = (float*)(smw + OFF_COS);
    __shared__ int sLast;

    const int tid  = threadIdx.x;
    const int wid  = tid >> 5;
    const int lane = tid & 31;
    const int gid  = lane >> 2;
    const int tg   = lane & 3;
    const int fl   = lane & 15;            // ldmatrix row-lane (non-trans)
    const int kh   = (lane >> 4) << 2;     // ldmatrix k-half (non-trans)
    const int sRow = (lane & 7) + ((lane >> 4) << 3);  // trans-ldsm sample row
    const int fSel = ((lane >> 3) & 1) << 2;           // trans-ldsm feature half (words)
    const int cta  = blockIdx.x;
    const int row0 = cta * ROWS;

    // ---- prefetch raw fp32 X into smem (overlaps the entire gram phase) ----
    {
        const uint32_t xrb = smem_u32(smw + OFF_XRAW);
#pragma unroll
        for (int i = 0; i < 8; i++) {
            int idx = tid + i * NTHR;         // 4096 x 16B chunks
            int which = idx >> 11;
            int rem = idx & 2047;
            int row = rem >> 5, c = rem & 31;
            const float* src = (which ? zxt : zxs) + (size_t)(row0 + row) * DIM + c * 4;
            cp16(xrb + (uint32_t)((which * ROWS + row) * XRP + c * 4) * 4, src);
        }
        CP_COMMIT();
    }

    // ---- phase 0: load + normalize Y (BOTH tensors front-batched: MLP 8) ----
    {
        int r = tid >> 3, part = tid & 7;
        const float4* s0 = (const float4*)(zys + (size_t)(row0 + r) * DIM) + part * 4;
        const float4* s1 = (const float4*)(zyt + (size_t)(row0 + r) * DIM) + part * 4;
        float4 v0[4], v1[4];
#pragma unroll
        for (int i = 0; i < 4; i++) v0[i] = s0[i];
#pragma unroll
        for (int i = 0; i < 4; i++) v1[i] = s1[i];
        float ss0 = 0.f, ss1 = 0.f;
#pragma unroll
        for (int i = 0; i < 4; i++) {
            ss0 += v0[i].x * v0[i].x + v0[i].y * v0[i].y + v0[i].z * v0[i].z + v0[i].w * v0[i].w;
            ss1 += v1[i].x * v1[i].x + v1[i].y * v1[i].y + v1[i].z * v1[i].z + v1[i].w * v1[i].w;
        }
#pragma unroll
        for (int off = 1; off < 8; off <<= 1) {
            ss0 += __shfl_xor_sync(0xffffffffu, ss0, off);
            ss1 += __shfl_xor_sync(0xffffffffu, ss1, off);
        }
        float inv0 = rsqrtf(fmaxf(ss0, 1e-24f));
        float inv1 = rsqrtf(fmaxf(ss1, 1e-24f));
        uint32_t* yb0 = smw + OFF_G + (size_t)r * YBP + part * 8;
        uint32_t* yb1 = smw + OFF_G + (size_t)(ROWS + r) * YBP + part * 8;
        const float* vf0 = (const float*)v0;
        const float* vf1 = (const float*)v1;
#pragma unroll
        for (int i = 0; i < 8; i++) {
            __nv_bfloat162 h0 = __floats2bfloat162_rn(vf0[2 * i] * inv0, vf0[2 * i + 1] * inv0);
            __nv_bfloat162 h1 = __floats2bfloat162_rn(vf1[2 * i] * inv1, vf1[2 * i + 1] * inv1);
            yb0[i] = *(uint32_t*)&h0;
            yb1[i] = *(uint32_t*)&h1;
        }
    }
    __syncthreads();

    // ---- phase 1: gram partials via bf16 mma + trans-ldsm, warp tile 32x32 ----
    {
        const int m0q = (wid & 3) * 32;
        const int n0q = (wid >> 2) * 32;
        const uint32_t ytb = smem_u32(smw + OFF_G);
#pragma unroll 1
        for (int m = 0; m < 3; m++) {
            const uint32_t aB = ytb + (m == 1 ? ROWS * YBP * 4 : 0);
            const uint32_t bB = ytb + (m == 0 ? 0 : ROWS * YBP * 4);
            float acc[8][4];
#pragma unroll
            for (int t = 0; t < 8; t++)
#pragma unroll
                for (int j = 0; j < 4; j++) acc[t][j] = 0.f;

#pragma unroll
            for (int k0 = 0; k0 < ROWS; k0 += 16) {     // k-step = 16 samples
                uint32_t A[2][4], B[2][4];
                uint32_t rowOff = (uint32_t)((k0 + sRow) * YBP + fSel) * 4;
#pragma unroll
                for (int mt = 0; mt < 2; mt++)
                    ldsm_x4_trans(A[mt], aB + rowOff + (uint32_t)((m0q + mt * 16) >> 1) * 4);
#pragma unroll
                for (int p = 0; p < 2; p++)
                    ldsm_x4_trans(B[p], bB + rowOff + (uint32_t)((n0q + p * 16) >> 1) * 4);
#pragma unroll
                for (int mt = 0; mt < 2; mt++)
#pragma unroll
                    for (int t = 0; t < 4; t++) {
                        int p = t >> 1, sub = t & 1;
                        mma_bf16(acc[mt * 4 + t], A[mt], B[p][sub], B[p][2 + sub]);
                    }
            }
            uint32_t* dst = &g_gram_part_bf[cta][m][0][0];
#pragma unroll
            for (int mt = 0; mt < 2; mt++) {
                int r1 = m0q + mt * 16 + gid, r2 = r1 + 8;
#pragma unroll
                for (int t = 0; t < 4; t++) {
                    int cw = ((n0q + t * 8) >> 1) + tg;
                    __nv_bfloat162 h1 = __floats2bfloat162_rn(acc[mt * 4 + t][0], acc[mt * 4 + t][1]);
                    __nv_bfloat162 h2 = __floats2bfloat162_rn(acc[mt * 4 + t][2], acc[mt * 4 + t][3]);
                    dst[r1 * (DIM / 2) + cw] = *(uint32_t*)&h1;
                    dst[r2 * (DIM / 2) + cw] = *(uint32_t*)&h2;
                }
            }
        }
    }

    // ---- arrive barrier 1; convert prefetched X (already in smem) ----
    grid_arrive(&g_ctr1, tid);
    CP_WAIT(0);
    __syncthreads();
    {
        int r = tid >> 3, part = tid & 7;
#pragma unroll 1
        for (int which = 0; which < 2; which++) {
            const float* xr = (const float*)(smw + OFF_XRAW + (size_t)(which * ROWS + r) * XRP);
            float4 v[4];
            float ss = 0.f;
#pragma unroll
            for (int i = 0; i < 4; i++) {
                v[i] = *(const float4*)(xr + part * 4 + i * 32);
                ss += v[i].x * v[i].x + v[i].y * v[i].y + v[i].z * v[i].z + v[i].w * v[i].w;
            }
            ss += __shfl_xor_sync(0xffffffffu, ss, 1);
            ss += __shfl_xor_sync(0xffffffffu, ss, 2);
            ss += __shfl_xor_sync(0xffffffffu, ss, 4);
            float inv = rsqrtf(fmaxf(ss, 1e-24f));
            uint32_t* xb = smw + OFF_XB + (size_t)(which * ROWS + r) * XBP;
#pragma unroll
            for (int i = 0; i < 4; i++) {
                __nv_bfloat162 h0 = __floats2bfloat162_rn(v[i].x * inv, v[i].y * inv);
                __nv_bfloat162 h1 = __floats2bfloat162_rn(v[i].z * inv, v[i].w * inv);
                xb[part * 2 + i * 16]     = *(uint32_t*)&h0;
                xb[part * 2 + i * 16 + 1] = *(uint32_t*)&h1;
            }
        }
    }
    grid_spin(&g_ctr1, NCTA, tid);

    // ---- phase 2: reduce bf16 partials (fixed order; unroll 32 -> MLP 32) ----
    {
        if (tid < 384) {
            int t192 = tid % 192;
            int half = tid / 192;
            int e = cta * 192 + t192;
            const uint32_t* base = &g_gram_part_bf[0][0][0][0]
                                 + (size_t)(half * 64) * (3 * DIM * (DIM / 2));
            float s0 = 0.f, s1 = 0.f;
#pragma unroll 32
            for (int p = 0; p < 64; p++) {
                uint32_t u = base[(size_t)p * (3 * DIM * (DIM / 2)) + e];
                float2 f = __bfloat1622float2(*(__nv_bfloat162*)&u);
                s0 += f.x; s1 += f.y;
            }
            sP[(half * 192 + t192) * 2]     = s0;
            sP[(half * 192 + t192) * 2 + 1] = s1;
        }
        __syncthreads();
        if (tid < 192) {
            int e = cta * 192 + tid;
            float a0 = sP[tid * 2]     + sP[(192 + tid) * 2];
            float a1 = sP[tid * 2 + 1] + sP[(192 + tid) * 2 + 1];
            int mat = e >> 13, rem = e & 8191, a = rem >> 6, pw = rem & 63;
            g_gramT[mat][2 * pw][a]     = __float2bfloat16(a0);
            g_gramT[mat][2 * pw + 1][a] = __float2bfloat16(a1);
        }
    }
    grid_arrive(&g_ctr2, tid);
    grid_spin(&g_ctr2, NCTA, tid);

    // ---- phase 3: stage G in 2 groups (mat0 | mats 1-2); early-start mat 0 ----
    {
        const uint32_t gb = smem_u32(smw + OFF_G);
        const char* gsrc = (const char*)&g_gramT[0][0][0];
#pragma unroll
        for (int i = 0; i < 4; i++) {                  // mat 0: idx 0..2047
            int idx = tid + i * NTHR;
            int row = idx >> 4, c = idx & 15;
            cp16(gb + (uint32_t)(row * BGP * 4 + c * 16), gsrc + idx * 16);
        }
        CP_COMMIT();
#pragma unroll
        for (int i = 4; i < 12; i++) {                 // mats 1-2: idx 2048..6143
            int idx = tid + i * NTHR;
            int mat = idx >> 11;
            int rem = idx & 2047;
            int row = rem >> 4, c = rem & 15;
            cp16(gb + (uint32_t)((mat * DIM + row) * BGP * 4 + c * 16), gsrc + idx * 16);
        }
        CP_COMMIT();

        const int m0 = (wid & 3) * 16;
        const int nq = wid >> 2;
        const uint32_t xbb = smem_u32(smw + OFF_XB);

#pragma unroll 1
        for (int m = 0; m < 3; m++) {
            if (m == 0) CP_WAIT(1);
            else if (m == 1) CP_WAIT(0);
            if (m < 2) __syncthreads();                // staged data visible to all

            const uint32_t bGb = gb + (uint32_t)(m * DIM * BGP) * 4;
            const uint32_t xab = xbb + (m == 1 ? ROWS * XBP * 4 : 0);
            const uint32_t* Xb = smw + OFF_XB + (m == 0 ? 0 : ROWS * XBP);

            float acc[4][4];
#pragma unroll
            for (int t = 0; t < 4; t++)
#pragma unroll
                for (int j = 0; j < 4; j++) acc[t][j] = 0.f;

#pragma unroll 2
            for (int k0h = 0; k0h < 64; k0h += 8) {      // 8 k-steps of 16
                uint32_t A[4], B[2][4];
                ldsm_x4(A, xab + (uint32_t)((m0 + fl) * XBP + k0h + kh) * 4);
#pragma unroll
                for (int p = 0; p < 2; p++) {
                    int f = nq * 32 + p * 16 + fl;
                    ldsm_x4(B[p], bGb + (uint32_t)(f * BGP + k0h + kh) * 4);
                }
#pragma unroll
                for (int t = 0; t < 4; t++) {
                    int p = t >> 1, sub = t & 1;
                    mma_bf16(acc[t], A, B[p][sub], B[p][2 + sub]);
                }
            }

            float p1 = 0.f, p2 = 0.f;
#pragma unroll
            for (int t = 0; t < 4; t++) {
                int n0 = nq * 32 + t * 8;
                uint32_t xw1 = Xb[(m0 + gid) * XBP + (n0 >> 1) + tg];
                uint32_t xw2 = Xb[(m0 + 8 + gid) * XBP + (n0 >> 1) + tg];
                float2 f1 = __bfloat1622float2(*(__nv_bfloat162*)&xw1);
                float2 f2 = __bfloat1622float2(*(__nv_bfloat162*)&xw2);
                p1 += acc[t][0] * f1.x + acc[t][1] * f1.y;
                p2 += acc[t][2] * f2.x + acc[t][3] * f2.y;
            }
            p1 += __shfl_xor_sync(0xffffffffu, p1, 1);
            p1 += __shfl_xor_sync(0xffffffffu, p1, 2);
            p2 += __shfl_xor_sync(0xffffffffu, p2, 1);
            p2 += __shfl_xor_sync(0xffffffffu, p2, 2);
            if (tg == 0) {
                sP[(m * 4 + nq) * ROWS + m0 + gid]     = p1;
                sP[(m * 4 + nq) * ROWS + m0 + 8 + gid] = p2;
            }
        }
    }
    __syncthreads();

    // ---- cosines + per-CTA partial ----
    if (tid < ROWS) {
        float A = sP[0 * ROWS + tid] + sP[1 * ROWS + tid] + sP[2 * ROWS + tid] + sP[3 * ROWS + tid];
        float B = sP[4 * ROWS + tid] + sP[5 * ROWS + tid] + sP[6 * ROWS + tid] + sP[7 * ROWS + tid];
        float C = sP[8 * ROWS + tid] + sP[9 * ROWS + tid] + sP[10 * ROWS + tid] + sP[11 * ROWS + tid];
        sCos[tid] = C * rsqrtf(fmaxf(A * B, 1e-30f));
    }
    __syncthreads();
    if (tid == 0) {
        float s = 0.f;
#pragma unroll 8
        for (int i = 0; i < ROWS; i++) s += sCos[i];
        g_loss_part[cta] = s;
        __threadfence();
        int v = atomicAdd(&g_ctr3, 1);
        sLast = (v == NCTA - 1);
    }
    __syncthreads();

    // ---- last CTA: final reduction, write loss, reset counters ----
    if (sLast) {
        __threadfence();
        __shared__ float w[4];
        if (tid < NCTA) {
            float v = g_loss_part[tid];
#pragma unroll
            for (int off = 16; off > 0; off >>= 1)
                v += __shfl_xor_sync(0xffffffffu, v, off);
            if ((tid & 31) == 0) w[tid >> 5] = v;
        }
        __syncthreads();
        if (tid == 0) {
            float s = w[0] + w[1] + w[2] + w[3];
            const float b = (float)BSZ;
            out[0] = (2.f * b - 2.f * s) / (b * b);
            g_ctr1 = 0; g_ctr2 = 0; g_ctr3 = 0;   // reset for next graph replay
            __threadfence();
        }
    }
}

// ============================================================================
extern "C" void kernel_launch(void* const* d_in, const int* in_sizes, int n_in,
                              void* d_out, int out_size) {
    (void)in_sizes; (void)n_in; (void)out_size;
    const float* zxs = (const float*)d_in[0];
    const float* zys = (const float*)d_in[1];
    const float* zxt = (const float*)d_in[2];
    const float* zyt = (const float*)d_in[3];
    // temperature (d_in[4]) cancels exactly under row-normalization.

    cudaFuncSetAttribute(fused_kernel, cudaFuncAttributeMaxDynamicSharedMemorySize,
                         FUSED_SMEM_BYTES);

    fused_kernel<<<NCTA, NTHR, FUSED_SMEM_BYTES>>>(zxs, zys, zxt, zyt, (float*)d_out);
}